// round 14
// baseline (speedup 1.0000x reference)
#include <cuda_runtime.h>
#include <cstdint>
#include <math.h>

#define BATCH 64
#define SEQ   2048
#define INP   256
#define HID   512
#define NCTA  128
#define THR   512
#define BGR   8      // batches per CTA
#define JGR   32     // hidden columns per CTA
#define FSTR  32     // flag stride in u32 (128B = own L2 line per flag)

// ---------------- scratch (no allocations allowed) ----------------
__device__ float    g_hbuf[2 * BATCH * HID];     // double-buffered hidden state
__device__ float    g_opart[NCTA * 16];          // per-CTA readout partials
__device__ unsigned g_flags[NCTA * FSTR];        // per-CTA epoch flags, one L2 line each

// ---------------- packed fp32x2 FMA helpers (FFMA2) ----------------
__device__ __forceinline__ void fma2(unsigned long long &d, unsigned long long a, unsigned long long b) {
    asm("fma.rn.f32x2 %0, %1, %2, %0;" : "+l"(d) : "l"(a), "l"(b));
}
__device__ __forceinline__ unsigned long long pack2(float lo, float hi) {
    unsigned long long r;
    asm("mov.b64 %0, {%1, %2};" : "=l"(r) : "f"(lo), "f"(hi));
    return r;
}
__device__ __forceinline__ float lo2(unsigned long long v) { return __uint_as_float((unsigned)v); }
__device__ __forceinline__ float hi2(unsigned long long v) { return __uint_as_float((unsigned)(v >> 32)); }

// ---------------- sync ops (no scope>=cluster FENCES in step path) ----------------
__device__ __forceinline__ unsigned ldacq(const unsigned* p) {
    unsigned v;
    asm volatile("ld.acquire.gpu.global.u32 %0, [%1];" : "=r"(v) : "l"(p) : "memory");
    return v;
}
__device__ __forceinline__ void strel(unsigned* p, unsigned v) {
    asm volatile("st.release.gpu.global.u32 [%0], %1;" :: "l"(p), "r"(v) : "memory");
}

// ---------------- cp.async helpers ----------------
__device__ __forceinline__ uint32_t smem_u32(const void* p) {
    uint32_t a;
    asm("{ .reg .u64 t; cvta.to.shared.u64 t, %1; cvt.u32.u64 %0, t; }" : "=r"(a) : "l"(p));
    return a;
}
__device__ __forceinline__ void cpasync16(uint32_t dst, const void* src) {
    asm volatile("cp.async.cg.shared.global [%0], [%1], 16;" :: "r"(dst), "l"(src));
}
#define CP_COMMIT() asm volatile("cp.async.commit_group;" ::: "memory")
#define CP_WAIT1()  asm volatile("cp.async.wait_group 1;" ::: "memory")

// 4-stage butterfly over a[16] + final xor-1 fold (R9-verified mapping):
// afterwards EVEN lane L holds output o=(L>>1)&15.
#define BFLY16(a, lane)                                                     \
    do {                                                                    \
        _Pragma("unroll")                                                   \
        for (int off = 16, nk = 8; off >= 2; off >>= 1, nk >>= 1) {         \
            const bool up = ((lane) & off) != 0;                            \
            _Pragma("unroll")                                               \
            for (int i = 0; i < nk; i++) {                                  \
                float send = up ? (a)[i] : (a)[i + nk];                     \
                float recv = __shfl_xor_sync(0xffffffffu, send, off);       \
                (a)[i] = (up ? (a)[i + nk] : (a)[i]) + recv;                \
            }                                                               \
        }                                                                   \
        (a)[0] += __shfl_xor_sync(0xffffffffu, (a)[0], 1);                  \
    } while (0)

// =====================================================================
// ONE persistent kernel, 128 CTAs x 512 threads (16 warps = 4/SMSP).
// cta = bg*16+jg -> 8 batches x 32 hidden cols. Warp w: batches
// (w>>3)*4..+3, cols (w&7)*4..+3 (4b x 4j tile, K over 32 lanes in
// quads). U (4 quads) and W (2 quads) slices live in registers. wx is
// pipelined one step ahead (cp.async X prefetch two ahead), computed in
// the h-stage LDG shadow. Sync: per-CTA epoch flags, ONE L2 LINE EACH
// (16-slice-parallel poll, own flag skipped); h published as 16
// coalesced 128B lines by warp 0 followed by syncwarp + lane0 release.
// =====================================================================
__global__ __launch_bounds__(THR, 1)
void fused_kernel(const float* __restrict__ x,  const float* __restrict__ Ww,
                  const float* __restrict__ Wb, const float* __restrict__ Uw,
                  const float* __restrict__ Ub, const float* __restrict__ Vw,
                  const float* __restrict__ Vb, float* __restrict__ out) {
    __shared__ float Xsh[2][BGR * INP];   // 16 KB, double-buffered X tiles
    __shared__ float hsh[BGR * HID];      // 16 KB
    __shared__ float houtsh[BGR * JGR];   // 1 KB: this CTA's h outputs [8][32]

    const int t    = threadIdx.x;
    const int cta  = blockIdx.x;
    const int bg   = cta >> 4;
    const int jg   = cta & 15;
    const int b0   = bg * BGR;
    const int j0   = jg * JGR;
    const int w    = t >> 5;
    const int lane = t & 31;
    const int wb   = w >> 3;      // batch half -> batches wb*4..+3
    const int wj   = w & 7;       // j group -> cols wj*4..+3

    // writer mapping: even lane L -> o=(L>>1): b=(L>>3)&3, jl=(L>>1)&3
    const int ob  = (lane >> 3) & 3;
    const int ojl = (lane >> 1) & 3;
    const bool writer = ((lane & 1) == 0);
    const int jabs  = j0 + wj * 4 + ojl;           // absolute hidden col (writers)

    unsigned* const fgrp = g_flags + bg * 16 * FSTR;
    const unsigned base = g_flags[cta * FSTR];     // replay-safe epoch base

    // ---- one-time: U slice (4 quads) and W slice (2 quads) into registers ----
    ulonglong2 ureg[4][4], wreg[2][4];
#pragma unroll
    for (int qi = 0; qi < 4; qi++) {
        const int kb = qi * 128 + lane * 4;
#pragma unroll
        for (int j = 0; j < 4; j++) {
            const float* up = Uw + (size_t)kb * HID + (j0 + wj * 4 + j);
            ureg[qi][j].x = pack2(up[0], up[HID]);
            ureg[qi][j].y = pack2(up[2 * HID], up[3 * HID]);
        }
    }
#pragma unroll
    for (int qi = 0; qi < 2; qi++) {
        const int kb = qi * 128 + lane * 4;
#pragma unroll
        for (int j = 0; j < 4; j++) {
            const float* wp = Ww + (size_t)kb * HID + (j0 + wj * 4 + j);
            wreg[qi][j].x = pack2(wp[0], wp[HID]);
            wreg[qi][j].y = pack2(wp[2 * HID], wp[3 * HID]);
        }
    }
    const float ubj = Ub[jabs];
    const float wbj = Wb[jabs];

    // ---- X staging: thread t copies its single 16B chunk (512 x 16B = 8KB) ----
    const int xr = t >> 6;                 // batch row 0..7
    const int xc = t & 63;                 // float4 col 0..63
    const float* const xsrc = x + ((size_t)(b0 + xr) * SEQ) * INP + xc * 4;
    const uint32_t xdst0 = smem_u32(&Xsh[0][xr * INP + xc * 4]);
    const uint32_t xdst1 = smem_u32(&Xsh[1][xr * INP + xc * 4]);
#define STAGE_X(sp) cpasync16(((sp) & 1) ? xdst1 : xdst0, xsrc + (size_t)(sp) * INP)

    // h publication descriptor (warp 0): f4 indices lane and lane+32 of houtsh
    const int p0r = lane >> 3,        p0c = lane & 7;          // row, f4col of idx lane
    const int p1r = (lane + 32) >> 3, p1c = lane & 7;          // idx lane+32

    // wx for step sp from Xsh[sp&1] + wreg; valid on even lanes
#define WX_COMPUTE(sp, dst)                                                             \
    do {                                                                                \
        unsigned long long wacc[16];                                                    \
        _Pragma("unroll")                                                               \
        for (int o = 0; o < 16; o++) wacc[o] = 0ull;                                    \
        const float* xb = Xsh[(sp) & 1];                                                \
        _Pragma("unroll")                                                               \
        for (int qi = 0; qi < 2; qi++) {                                                \
            const int kb = qi * 128 + lane * 4;                                         \
            ulonglong2 xq[4];                                                           \
            _Pragma("unroll")                                                           \
            for (int b = 0; b < 4; b++)                                                 \
                xq[b] = *(const ulonglong2*)(xb + (wb * 4 + b) * INP + kb);             \
            _Pragma("unroll")                                                           \
            for (int b = 0; b < 4; b++)                                                 \
                _Pragma("unroll")                                                       \
                for (int j = 0; j < 4; j++) {                                           \
                    fma2(wacc[b * 4 + j], xq[b].x, wreg[qi][j].x);                      \
                    fma2(wacc[b * 4 + j], xq[b].y, wreg[qi][j].y);                      \
                }                                                                       \
        }                                                                               \
        float vv[16];                                                                   \
        _Pragma("unroll")                                                               \
        for (int o = 0; o < 16; o++) vv[o] = lo2(wacc[o]) + hi2(wacc[o]);               \
        BFLY16(vv, lane);                                                               \
        (dst) = vv[0] + wbj;                                                            \
    } while (0)

    // ---- prologue ----
    STAGE_X(0); CP_COMMIT();
    STAGE_X(1); CP_COMMIT();
    CP_WAIT1();
    __syncthreads();
    float wx_cur;
    WX_COMPUTE(0, wx_cur);
    float h_last = 0.0f;

    for (int s = 0; s < SEQ; s++) {
        // 1. prefetch X(s+2); wait X(s+1); warp0 polls flags for h(s)
        if (s + 2 < SEQ) STAGE_X(s + 2);
        CP_COMMIT();
        CP_WAIT1();
        if (w == 0 && s > 0) {
            const unsigned tgt = base + (unsigned)s;
            unsigned v = tgt;
            if (lane < 16 && lane != jg) v = ldacq(fgrp + lane * FSTR);
            while (__any_sync(0xffffffffu, (int)(v - tgt) < 0)) {
                if (lane < 16 && lane != jg && (int)(v - tgt) < 0)
                    v = ldacq(fgrp + lane * FSTR);
            }
        }
        __syncthreads();   // bar1: X(s+1) visible; h(s) published; hsh reusable

        // 2. stage h(s) (LDGs first), wx(s+1) in the LDG shadow
        float4 hv0, hv1;
        if (s > 0) {
            const float* hsrc = g_hbuf + (s & 1) * (BATCH * HID) + (size_t)b0 * HID;
            hv0 = ((const float4*)hsrc)[t];
            hv1 = ((const float4*)hsrc)[t + THR];
        }
        float wx_next = 0.0f;
        if (s + 1 < SEQ) WX_COMPUTE(s + 1, wx_next);
        if (s > 0) {
            ((float4*)hsh)[t]       = hv0;
            ((float4*)hsh)[t + THR] = hv1;
        } else {
            ((float4*)hsh)[t]       = make_float4(0.f, 0.f, 0.f, 0.f);
            ((float4*)hsh)[t + THR] = make_float4(0.f, 0.f, 0.f, 0.f);
        }
        __syncthreads();   // bar2: hsh ready

        // 3. scan compute: 4b x 4j FFMA2 tile, U from registers
        unsigned long long acc[16];
#pragma unroll
        for (int o = 0; o < 16; o++) acc[o] = 0ull;
#pragma unroll
        for (int qi = 0; qi < 4; qi++) {
            const int kb = qi * 128 + lane * 4;
            ulonglong2 hq[4];
#pragma unroll
            for (int b = 0; b < 4; b++)
                hq[b] = *(const ulonglong2*)(hsh + (wb * 4 + b) * HID + kb);
#pragma unroll
            for (int b = 0; b < 4; b++)
#pragma unroll
                for (int j = 0; j < 4; j++) {
                    fma2(acc[b * 4 + j], hq[b].x, ureg[qi][j].x);
                    fma2(acc[b * 4 + j], hq[b].y, ureg[qi][j].y);
                }
        }
        float v[16];
#pragma unroll
        for (int o = 0; o < 16; o++) v[o] = lo2(acc[o]) + hi2(acc[o]);
        BFLY16(v, lane);

        if (writer) {
            float hnew = tanhf(wx_cur + ubj + v[0]);
            h_last = hnew;
            houtsh[(wb * 4 + ob) * JGR + wj * 4 + ojl] = hnew;
        }

        // 4. publish h: warp0 emits 16 coalesced 128B lines, lane0 releases.
        __syncthreads();   // bar3: houtsh complete; orders all writers before warp0
        if (w == 0) {
            float* hdst = g_hbuf + ((s + 1) & 1) * (BATCH * HID) + (size_t)b0 * HID + j0;
            float4 a0 = ((const float4*)houtsh)[lane];
            float4 a1 = ((const float4*)houtsh)[lane + 32];
            *(float4*)(hdst + (size_t)p0r * HID + p0c * 4) = a0;
            *(float4*)(hdst + (size_t)p1r * HID + p1c * 4) = a1;
            __syncwarp();
            if (lane == 0) strel(g_flags + cta * FSTR, base + (unsigned)s + 1u);
        }
        // other warps run ahead into the next iteration's cp.async staging;
        // bar1 re-synchronizes with warp0.

        wx_cur = wx_next;
    }

    // ---- fused readout ----
    // houtsh still holds the final h tile [8][32]
    __syncthreads();
    if (w == 0 && lane < 16) {
        const int b = lane >> 1, o = lane & 1;
        float p = 0.0f;
#pragma unroll
        for (int j = 0; j < 32; j++)
            p += houtsh[b * JGR + j] * Vw[(size_t)(j0 + j) * 2 + o];
        g_opart[cta * 16 + lane] = p;
    }
    __syncthreads();
    if (t == 0) strel(g_flags + cta * FSTR, base + (unsigned)SEQ + 1u);

    if (jg == 0) {
        if (w == 0) {
            const unsigned tgt = base + (unsigned)SEQ + 1u;
            unsigned v2 = tgt;
            if (lane < 16) v2 = ldacq(fgrp + lane * FSTR);
            while (__any_sync(0xffffffffu, (int)(v2 - tgt) < 0)) {
                if (lane < 16 && (int)(v2 - tgt) < 0) v2 = ldacq(fgrp + lane * FSTR);
            }
        }
        __syncthreads();
        if (w == 0 && lane < 16) {
            const int b = lane >> 1, o = lane & 1;
            float ssum = Vb[o];
#pragma unroll
            for (int g = 0; g < 16; g++)
                ssum += g_opart[(bg * 16 + g) * 16 + lane];
            out[(size_t)(b0 + b) * 2 + o] = 1.0f / (1.0f + expf(-ssum));
        }
    }
}

// =====================================================================
extern "C" void kernel_launch(void* const* d_in, const int* in_sizes, int n_in,
                              void* d_out, int out_size) {
    const float* x  = (const float*)d_in[0];
    const float* Ww = (const float*)d_in[1];
    const float* Wb = (const float*)d_in[2];
    const float* Uw = (const float*)d_in[3];
    const float* Ub = (const float*)d_in[4];
    const float* Vw = (const float*)d_in[5];
    const float* Vb = (const float*)d_in[6];
    float* out = (float*)d_out;

    fused_kernel<<<NCTA, THR>>>(x, Ww, Wb, Uw, Ub, Vw, Vb, out);
}

// round 15
// speedup vs baseline: 1.3961x; 1.3961x over previous
#include <cuda_runtime.h>
#include <cstdint>
#include <math.h>

#define BATCH 64
#define SEQ   2048
#define INP   256
#define HID   512
#define NCTA  256    // 16 groups x 16 jg-slices
#define THR   256
#define NGRP  16     // batch groups
#define BGR   4      // batches per group/CTA
#define JGR   32     // hidden columns per CTA

// ---------------- scratch (no allocations allowed) ----------------
__device__ float    g_hbuf[2 * BATCH * HID];   // double-buffered hidden state
__device__ float    g_opart[NCTA * 8];         // per-CTA readout partials
__device__ unsigned g_flags[NCTA];             // per-CTA epoch flags (monotone across replays)

// ---------------- packed fp32x2 FMA helpers (FFMA2) ----------------
__device__ __forceinline__ void fma2(unsigned long long &d, unsigned long long a, unsigned long long b) {
    asm("fma.rn.f32x2 %0, %1, %2, %0;" : "+l"(d) : "l"(a), "l"(b));
}
__device__ __forceinline__ unsigned long long pack2(float lo, float hi) {
    unsigned long long r;
    asm("mov.b64 %0, {%1, %2};" : "=l"(r) : "f"(lo), "f"(hi));
    return r;
}
__device__ __forceinline__ float lo2(unsigned long long v) { return __uint_as_float((unsigned)v); }
__device__ __forceinline__ float hi2(unsigned long long v) { return __uint_as_float((unsigned)(v >> 32)); }

// ---------------- sync ops (no scope>=cluster FENCES in step path) ----------------
__device__ __forceinline__ unsigned ldacq(const unsigned* p) {
    unsigned v;
    asm volatile("ld.acquire.gpu.global.u32 %0, [%1];" : "=r"(v) : "l"(p) : "memory");
    return v;
}
__device__ __forceinline__ void strel(unsigned* p, unsigned v) {
    asm volatile("st.release.gpu.global.u32 [%0], %1;" :: "l"(p), "r"(v) : "memory");
}

// ---------------- cp.async helpers ----------------
__device__ __forceinline__ uint32_t smem_u32(const void* p) {
    uint32_t a;
    asm("{ .reg .u64 t; cvta.to.shared.u64 t, %1; cvt.u32.u64 %0, t; }" : "=r"(a) : "l"(p));
    return a;
}
__device__ __forceinline__ void cpasync16(uint32_t dst, const void* src) {
    asm volatile("cp.async.cg.shared.global [%0], [%1], 16;" :: "r"(dst), "l"(src));
}
#define CP_COMMIT() asm volatile("cp.async.commit_group;" ::: "memory")
#define CP_WAIT1()  asm volatile("cp.async.wait_group 1;" ::: "memory")

// 4-stage butterfly over a[16] + final xor-1 fold (verified mapping):
// afterwards EVEN lane L holds output o=(L>>1)&15: b=(L>>3)&3, jl=(L>>1)&3.
#define BFLY16(a, lane)                                                     \
    do {                                                                    \
        _Pragma("unroll")                                                   \
        for (int off = 16, nk = 8; off >= 2; off >>= 1, nk >>= 1) {         \
            const bool up = ((lane) & off) != 0;                            \
            _Pragma("unroll")                                               \
            for (int i = 0; i < nk; i++) {                                  \
                float send = up ? (a)[i] : (a)[i + nk];                     \
                float recv = __shfl_xor_sync(0xffffffffu, send, off);       \
                (a)[i] = (up ? (a)[i + nk] : (a)[i]) + recv;                \
            }                                                               \
        }                                                                   \
        (a)[0] += __shfl_xor_sync(0xffffffffu, (a)[0], 1);                  \
    } while (0)

// =====================================================================
// ONE persistent kernel: 256 CTAs x 256 threads, 2 CTAs resident per SM
// (launch_bounds(256,2) forces regs<=128 -> all 256 co-resident, no
// deadlock). cta = g*16+jg: batch group g (4 batches), 32 hidden cols.
// The two co-resident CTAs serve different groups -> one CTA's sync
// stalls are filled by the other's FMA work on the same SMSPs.
// Per-CTA: 8 warps, warp w = 4b x 4j (cols w*4..+3); U (4 quads) + W
// (2 quads) in registers; wx pipelined 1 step ahead (cp.async X, 2
// ahead); packed per-group flags (single coalesced poll line), warp-0
// acquire poll; distributed h publication; fused readout.
// =====================================================================
__global__ __launch_bounds__(THR, 2)
void fused_kernel(const float* __restrict__ x,  const float* __restrict__ Ww,
                  const float* __restrict__ Wb, const float* __restrict__ Uw,
                  const float* __restrict__ Ub, const float* __restrict__ Vw,
                  const float* __restrict__ Vb, float* __restrict__ out) {
    __shared__ float Xsh[2][BGR * INP];   // 8 KB, double-buffered X tiles
    __shared__ float hsh[BGR * HID];      // 8 KB

    const int t    = threadIdx.x;
    const int cta  = blockIdx.x;
    const int g    = cta >> 4;            // batch group 0..15
    const int jg   = cta & 15;
    const int b0   = g * BGR;
    const int j0   = jg * JGR;
    const int w    = t >> 5;              // 0..7
    const int lane = t & 31;
    const int wj   = w;                   // j group -> cols wj*4..+3

    // writer mapping: even lane L -> o=(L>>1): b=(L>>3)&3, jl=(L>>1)&3
    const int ob  = (lane >> 3) & 3;
    const int ojl = (lane >> 1) & 3;
    const bool writer = ((lane & 1) == 0);
    const int babs = b0 + ob;
    const int jabs = j0 + wj * 4 + ojl;

    unsigned* const fgrp = g_flags + g * 16;
    const unsigned base = g_flags[cta];   // replay-safe epoch base

    // ---- one-time: U slice (4 quads) + W slice (2 quads) into registers ----
    ulonglong2 ureg[4][4], wreg[2][4];
#pragma unroll
    for (int qi = 0; qi < 4; qi++) {
        const int kb = qi * 128 + lane * 4;
#pragma unroll
        for (int j = 0; j < 4; j++) {
            const float* up = Uw + (size_t)kb * HID + (j0 + wj * 4 + j);
            ureg[qi][j].x = pack2(up[0], up[HID]);
            ureg[qi][j].y = pack2(up[2 * HID], up[3 * HID]);
        }
    }
#pragma unroll
    for (int qi = 0; qi < 2; qi++) {
        const int kb = qi * 128 + lane * 4;
#pragma unroll
        for (int j = 0; j < 4; j++) {
            const float* wp = Ww + (size_t)kb * HID + (j0 + wj * 4 + j);
            wreg[qi][j].x = pack2(wp[0], wp[HID]);
            wreg[qi][j].y = pack2(wp[2 * HID], wp[3 * HID]);
        }
    }
    const float ubj = Ub[jabs];
    const float wbj = Wb[jabs];

    // ---- X staging: thread t copies its single 16B chunk (256 x 16B = 4KB) ----
    const int xr = t >> 6;                 // batch row 0..3
    const int xc = t & 63;                 // float4 col 0..63
    const float* const xsrc = x + ((size_t)(b0 + xr) * SEQ) * INP + xc * 4;
    const uint32_t xdst0 = smem_u32(&Xsh[0][xr * INP + xc * 4]);
    const uint32_t xdst1 = smem_u32(&Xsh[1][xr * INP + xc * 4]);
#define STAGE_X(sp) cpasync16(((sp) & 1) ? xdst1 : xdst0, xsrc + (size_t)(sp) * INP)

    // wx for step sp from Xsh[sp&1] + wreg; valid on even lanes
#define WX_COMPUTE(sp, dst)                                                             \
    do {                                                                                \
        unsigned long long wacc[16];                                                    \
        _Pragma("unroll")                                                               \
        for (int o = 0; o < 16; o++) wacc[o] = 0ull;                                    \
        const float* xb = Xsh[(sp) & 1];                                                \
        _Pragma("unroll")                                                               \
        for (int qi = 0; qi < 2; qi++) {                                                \
            const int kb = qi * 128 + lane * 4;                                         \
            ulonglong2 xq[4];                                                           \
            _Pragma("unroll")                                                           \
            for (int b = 0; b < 4; b++)                                                 \
                xq[b] = *(const ulonglong2*)(xb + b * INP + kb);                        \
            _Pragma("unroll")                                                           \
            for (int b = 0; b < 4; b++)                                                 \
                _Pragma("unroll")                                                       \
                for (int j = 0; j < 4; j++) {                                           \
                    fma2(wacc[b * 4 + j], xq[b].x, wreg[qi][j].x);                      \
                    fma2(wacc[b * 4 + j], xq[b].y, wreg[qi][j].y);                      \
                }                                                                       \
        }                                                                               \
        float vv[16];                                                                   \
        _Pragma("unroll")                                                               \
        for (int o = 0; o < 16; o++) vv[o] = lo2(wacc[o]) + hi2(wacc[o]);               \
        BFLY16(vv, lane);                                                               \
        (dst) = vv[0] + wbj;                                                            \
    } while (0)

    // ---- prologue ----
    STAGE_X(0); CP_COMMIT();
    STAGE_X(1); CP_COMMIT();
    CP_WAIT1();
    __syncthreads();
    float wx_cur;
    WX_COMPUTE(0, wx_cur);
    float h_last = 0.0f;

    for (int s = 0; s < SEQ; s++) {
        // 1. prefetch X(s+2); wait X(s+1); warp0 acquire-polls group flags
        if (s + 2 < SEQ) STAGE_X(s + 2);
        CP_COMMIT();
        CP_WAIT1();
        if (w == 0 && s > 0) {
            const unsigned tgt = base + (unsigned)s;
            unsigned v = tgt;
            if (lane < 16) v = ldacq(fgrp + lane);
            while (__any_sync(0xffffffffu, (int)(v - tgt) < 0)) {
                if (lane < 16 && (int)(v - tgt) < 0) v = ldacq(fgrp + lane);
            }
        }
        __syncthreads();   // bar1: X(s+1) visible; h(s) published; hsh reusable

        // 2. stage h(s) (LDGs first), wx(s+1) in the LDG shadow
        float4 hv0, hv1;
        if (s > 0) {
            const float* hsrc = g_hbuf + (s & 1) * (BATCH * HID) + (size_t)b0 * HID;
            hv0 = ((const float4*)hsrc)[t];
            hv1 = ((const float4*)hsrc)[t + THR];
        }
        float wx_next = 0.0f;
        if (s + 1 < SEQ) WX_COMPUTE(s + 1, wx_next);
        if (s > 0) {
            ((float4*)hsh)[t]       = hv0;
            ((float4*)hsh)[t + THR] = hv1;
        } else {
            ((float4*)hsh)[t]       = make_float4(0.f, 0.f, 0.f, 0.f);
            ((float4*)hsh)[t + THR] = make_float4(0.f, 0.f, 0.f, 0.f);
        }
        __syncthreads();   // bar2: hsh ready

        // 3. scan compute: 4b x 4j FFMA2 tile, U from registers
        unsigned long long acc[16];
#pragma unroll
        for (int o = 0; o < 16; o++) acc[o] = 0ull;
#pragma unroll
        for (int qi = 0; qi < 4; qi++) {
            const int kb = qi * 128 + lane * 4;
            ulonglong2 hq[4];
#pragma unroll
            for (int b = 0; b < 4; b++)
                hq[b] = *(const ulonglong2*)(hsh + b * HID + kb);
#pragma unroll
            for (int b = 0; b < 4; b++)
#pragma unroll
                for (int j = 0; j < 4; j++) {
                    fma2(acc[b * 4 + j], hq[b].x, ureg[qi][j].x);
                    fma2(acc[b * 4 + j], hq[b].y, ureg[qi][j].y);
                }
        }
        float v[16];
#pragma unroll
        for (int o = 0; o < 16; o++) v[o] = lo2(acc[o]) + hi2(acc[o]);
        BFLY16(v, lane);

        if (writer) {
            float hnew = tanhf(wx_cur + ubj + v[0]);
            h_last = hnew;
            g_hbuf[((s + 1) & 1) * (BATCH * HID) + (size_t)babs * HID + jabs] = hnew;
        }

        // 4. order h stores before release
        __syncthreads();   // bar3
        if (t == 0) strel(g_flags + cta, base + (unsigned)s + 1u);

        wx_cur = wx_next;
    }

    // ---- fused readout ----
    if (writer) hsh[ob * JGR + wj * 4 + ojl] = h_last;   // final tile [4][32]
    __syncthreads();
    if (w == 0 && lane < 8) {
        const int b = lane >> 1, o = lane & 1;
        float p = 0.0f;
#pragma unroll
        for (int j = 0; j < JGR; j++)
            p += hsh[b * JGR + j] * Vw[(size_t)(j0 + j) * 2 + o];
        g_opart[cta * 8 + lane] = p;
    }
    __syncthreads();
    if (t == 0) strel(g_flags + cta, base + (unsigned)SEQ + 1u);

    if (jg == 0) {
        if (w == 0) {
            const unsigned tgt = base + (unsigned)SEQ + 1u;
            unsigned v2 = tgt;
            if (lane < 16) v2 = ldacq(fgrp + lane);
            while (__any_sync(0xffffffffu, (int)(v2 - tgt) < 0)) {
                if (lane < 16 && (int)(v2 - tgt) < 0) v2 = ldacq(fgrp + lane);
            }
        }
        __syncthreads();
        if (w == 0 && lane < 8) {
            const int b = lane >> 1, o = lane & 1;
            float ssum = Vb[o];
#pragma unroll
            for (int gg = 0; gg < 16; gg++)
                ssum += g_opart[(g * 16 + gg) * 8 + lane];
            out[(size_t)(b0 + b) * 2 + o] = 1.0f / (1.0f + expf(-ssum));
        }
    }
}

// =====================================================================
extern "C" void kernel_launch(void* const* d_in, const int* in_sizes, int n_in,
                              void* d_out, int out_size) {
    const float* x  = (const float*)d_in[0];
    const float* Ww = (const float*)d_in[1];
    const float* Wb = (const float*)d_in[2];
    const float* Uw = (const float*)d_in[3];
    const float* Ub = (const float*)d_in[4];
    const float* Vw = (const float*)d_in[5];
    const float* Vb = (const float*)d_in[6];
    float* out = (float*)d_out;

    fused_kernel<<<NCTA, THR>>>(x, Ww, Wb, Uw, Ub, Vw, Vb, out);
}